// round 1
// baseline (speedup 1.0000x reference)
#include <cuda_runtime.h>
#include <cuda_bf16.h>
#include <math.h>

// ---------------- problem constants ----------------
#define T_DIM 4096
#define S_DIM 4096
#define B_DIM 8
#define E_DIM 1024
#define BUCKET 16
#define NB 256            // T/BUCKET
#define TAU 0.75f
// SCALE = E^-0.5 = 1/32 ; alpha = SCALE/TAU
#define ATTN_ALPHA (1.0f/(32.0f*0.75f))

// ---------------- scratch (device globals; no allocation allowed) ----------------
__device__ float g_qm[B_DIM*NB*E_DIM];      // bucket-mean of query   (B,256,E) rows m=b*256+i
__device__ float g_km[B_DIM*NB*E_DIM];
__device__ float g_qb[B_DIM*NB*E_DIM];      // projected bucket queries
__device__ float g_kb[B_DIM*NB*E_DIM];
__device__ float g_la[B_DIM*NB*NB];         // sinkhorn logits / normalized
__device__ float g_p [B_DIM*NB*NB];         // exp(la)
__device__ float g_rowsum[B_DIM*NB];
__device__ int   g_kpmb[B_DIM*NB];
__device__ float g_wvo[E_DIM*E_DIM];        // Wo @ Wv  (row-major E x E)
__device__ float g_bvo[E_DIM];              // Wo @ bv
__device__ float g_z [T_DIM*B_DIM*E_DIM];   // mixed raw value, (T,B,E) layout

// ---------------- bucket mean: qm[b*256+i][e] = mean_pos X[(16i+pos),b,e] ----------------
__global__ void bucket_mean_kernel(const float* __restrict__ X, float* __restrict__ out) {
    int o = blockIdx.x * 256 + threadIdx.x;            // 2048*1024 total
    int e = o & (E_DIM - 1);
    int m = o >> 10;                                   // b*256+i
    int b = m >> 8;
    int i = m & 255;
    const float* src = X + (size_t)(i * BUCKET) * (B_DIM * E_DIM) + b * E_DIM + e;
    float s = 0.f;
#pragma unroll
    for (int pos = 0; pos < BUCKET; pos++) s += src[(size_t)pos * (B_DIM * E_DIM)];
    out[o] = s * (1.0f / BUCKET);
}

// ---------------- bucketed key-padding mask ----------------
__global__ void kpmb_kernel(const unsigned char* __restrict__ mask, int* __restrict__ kpmb) {
    int j = blockIdx.x * 256 + threadIdx.x;            // 2048
    if (j >= B_DIM * NB) return;
    int b = j >> 8, s = j & 255;
    const unsigned char* m = mask + b * S_DIM + s * BUCKET;
    int all = 1;
#pragma unroll
    for (int t = 0; t < BUCKET; t++) all &= (m[t] != 0);
    kpmb[j] = all;
}

__global__ void mask_kernel(float* __restrict__ la, const int* __restrict__ kpmb) {
    int idx = blockIdx.x * 256 + threadIdx.x;          // 8*256*256
    int b = idx >> 16, i = (idx >> 8) & 255, j = idx & 255;
    if (kpmb[b * 256 + i] != kpmb[b * 256 + j]) la[idx] = -1e30f;
}

// ---------------- bvo = Wo @ bv ----------------
__global__ void bvo_kernel(const float* __restrict__ Wo, const float* __restrict__ bv,
                           float* __restrict__ bvo) {
    int g = blockIdx.x * 8 + (threadIdx.x >> 5);       // one warp per output row
    int l = threadIdx.x & 31;
    if (g >= E_DIM) return;
    float s = 0.f;
    for (int k = l; k < E_DIM; k += 32) s += Wo[(size_t)g * E_DIM + k] * bv[k];
#pragma unroll
    for (int off = 16; off; off >>= 1) s += __shfl_xor_sync(0xffffffffu, s, off);
    if (l == 0) bvo[g] = s;
}

// ---------------- generic fp32 tiled GEMM: C[m,n] = alpha * sum_k A[m,k]*B'[n,k] (+bias) ----------------
// BTRANS=false: B row-major (N,K) ;  BTRANS=true: B row-major (K,N) (reads B[k*N+n])
// RS: C += rowsum(m)*bvo[n]   (final output GEMM only; m = t*8+b layout)
template <bool BTRANS, bool BIAS, bool RS>
__global__ __launch_bounds__(256, 2)
void gemm128_kernel(float* __restrict__ C, const float* __restrict__ A, const float* __restrict__ B,
                    const float* __restrict__ bias, const float* __restrict__ bvo,
                    const float* __restrict__ rowsum,
                    int M, int N, int K, float alpha,
                    long sA, long sB, long sC) {
    __shared__ float As[8][132];
    __shared__ float Bs[8][132];
    int z = blockIdx.z;
    A += (long)z * sA; B += (long)z * sB; C += (long)z * sC;
    int bm = blockIdx.y * 128, bn = blockIdx.x * 128;
    int tid = threadIdx.x, tx = tid & 15, ty = tid >> 4;
    float acc[8][8];
#pragma unroll
    for (int i = 0; i < 8; i++)
#pragma unroll
        for (int j = 0; j < 8; j++) acc[i][j] = 0.f;

    for (int k0 = 0; k0 < K; k0 += 8) {
        {   // A tile: As[k][m]
            int row = tid >> 1, part = tid & 1;
            float4 a4 = *(const float4*)(A + (size_t)(bm + row) * K + k0 + part * 4);
            As[part * 4 + 0][row] = a4.x; As[part * 4 + 1][row] = a4.y;
            As[part * 4 + 2][row] = a4.z; As[part * 4 + 3][row] = a4.w;
        }
        if (!BTRANS) {
            int row = tid >> 1, part = tid & 1;
            float4 b4 = *(const float4*)(B + (size_t)(bn + row) * K + k0 + part * 4);
            Bs[part * 4 + 0][row] = b4.x; Bs[part * 4 + 1][row] = b4.y;
            Bs[part * 4 + 2][row] = b4.z; Bs[part * 4 + 3][row] = b4.w;
        } else {
            int kk = tid >> 5, n4 = (tid & 31) * 4;
            *(float4*)&Bs[kk][n4] = *(const float4*)(B + (size_t)(k0 + kk) * N + bn + n4);
        }
        __syncthreads();
#pragma unroll
        for (int k = 0; k < 8; k++) {
            float4 a0 = *(float4*)&As[k][ty * 8];
            float4 a1 = *(float4*)&As[k][ty * 8 + 4];
            float4 b0 = *(float4*)&Bs[k][tx * 8];
            float4 b1 = *(float4*)&Bs[k][tx * 8 + 4];
            float ra[8] = {a0.x, a0.y, a0.z, a0.w, a1.x, a1.y, a1.z, a1.w};
            float rb[8] = {b0.x, b0.y, b0.z, b0.w, b1.x, b1.y, b1.z, b1.w};
#pragma unroll
            for (int i = 0; i < 8; i++)
#pragma unroll
                for (int j = 0; j < 8; j++) acc[i][j] = fmaf(ra[i], rb[j], acc[i][j]);
        }
        __syncthreads();
    }

#pragma unroll
    for (int i = 0; i < 8; i++) {
        int m = bm + ty * 8 + i;
        float rs = 0.f;
        if (RS) rs = rowsum[((m & 7) << 8) | (m >> 7)];   // b=m&7, tb=m>>7
        float out[8];
#pragma unroll
        for (int j = 0; j < 8; j++) {
            int n = bn + tx * 8 + j;
            float v = acc[i][j] * alpha;
            if (BIAS) v += bias[n];
            if (RS)   v += rs * bvo[n];
            out[j] = v;
        }
        float4* dst = (float4*)(C + (size_t)m * N + bn + tx * 8);
        dst[0] = make_float4(out[0], out[1], out[2], out[3]);
        dst[1] = make_float4(out[4], out[5], out[6], out[7]);
    }
}

// ---------------- fused sinkhorn: one block per batch, la in global (L2-resident) ----------------
__global__ __launch_bounds__(1024, 1)
void sinkhorn_kernel(float* __restrict__ la, float* __restrict__ p, float* __restrict__ rowsum) {
    int b = blockIdx.x;
    float* base = la + b * (NB * NB);
    int tid = threadIdx.x, w = tid >> 5, l = tid & 31;
    __shared__ float sh[32 * 256];
    __shared__ float colv[256];

    for (int it = 0; it < 8; it++) {
        // ---- row logsumexp (warp-local, rows w*8+ri, cols ci*32+l) ----
#pragma unroll
        for (int ri = 0; ri < 8; ri++) {
            int r = w * 8 + ri;
            float v[8];
#pragma unroll
            for (int ci = 0; ci < 8; ci++) v[ci] = base[r * 256 + ci * 32 + l];
            float m = v[0];
#pragma unroll
            for (int ci = 1; ci < 8; ci++) m = fmaxf(m, v[ci]);
#pragma unroll
            for (int off = 16; off; off >>= 1) m = fmaxf(m, __shfl_xor_sync(0xffffffffu, m, off));
            float s = 0.f;
#pragma unroll
            for (int ci = 0; ci < 8; ci++) s += __expf(v[ci] - m);
#pragma unroll
            for (int off = 16; off; off >>= 1) s += __shfl_xor_sync(0xffffffffu, s, off);
            float lse = m + __logf(s);
#pragma unroll
            for (int ci = 0; ci < 8; ci++) base[r * 256 + ci * 32 + l] = v[ci] - lse;
        }
        __syncthreads();
        // ---- column logsumexp ----
        float pm[8];
#pragma unroll
        for (int ci = 0; ci < 8; ci++) pm[ci] = -3.4e38f;
#pragma unroll
        for (int ri = 0; ri < 8; ri++)
#pragma unroll
            for (int ci = 0; ci < 8; ci++)
                pm[ci] = fmaxf(pm[ci], base[(w * 8 + ri) * 256 + ci * 32 + l]);
#pragma unroll
        for (int ci = 0; ci < 8; ci++) sh[w * 256 + ci * 32 + l] = pm[ci];
        __syncthreads();
        if (tid < 256) {
            float m = sh[tid];
#pragma unroll 4
            for (int ww = 1; ww < 32; ww++) m = fmaxf(m, sh[ww * 256 + tid]);
            colv[tid] = m;
        }
        __syncthreads();
        float ps[8];
#pragma unroll
        for (int ci = 0; ci < 8; ci++) ps[ci] = 0.f;
#pragma unroll
        for (int ri = 0; ri < 8; ri++)
#pragma unroll
            for (int ci = 0; ci < 8; ci++)
                ps[ci] += __expf(base[(w * 8 + ri) * 256 + ci * 32 + l] - colv[ci * 32 + l]);
#pragma unroll
        for (int ci = 0; ci < 8; ci++) sh[w * 256 + ci * 32 + l] = ps[ci];
        __syncthreads();
        if (tid < 256) {
            float s = 0.f;
#pragma unroll 4
            for (int ww = 0; ww < 32; ww++) s += sh[ww * 256 + tid];
            colv[tid] += __logf(s);
        }
        __syncthreads();
#pragma unroll
        for (int ri = 0; ri < 8; ri++)
#pragma unroll
            for (int ci = 0; ci < 8; ci++)
                base[(w * 8 + ri) * 256 + ci * 32 + l] -= colv[ci * 32 + l];
        __syncthreads();
    }

    // ---- p = exp(la), rowsum ----
#pragma unroll
    for (int ri = 0; ri < 8; ri++) {
        int r = w * 8 + ri;
        float s = 0.f;
#pragma unroll
        for (int ci = 0; ci < 8; ci++) {
            float e = __expf(base[r * 256 + ci * 32 + l]);
            p[b * (NB * NB) + r * 256 + ci * 32 + l] = e;
            s += e;
        }
#pragma unroll
        for (int off = 16; off; off >>= 1) s += __shfl_xor_sync(0xffffffffu, s, off);
        if (l == 0) rowsum[b * 256 + r] = s;
    }
}

// ---------------- bucket mix on RAW value: Z[t,b,e] = sum_s p[b,t/16,s] * value[16s + t%16, b, e] ----
// grid: (etile=16, pos=16, b=8); block 256; tile = 256 tb x 64 e
__global__ __launch_bounds__(256, 2)
void zmix_kernel(const float* __restrict__ value, const float* __restrict__ p, float* __restrict__ Z) {
    int et = blockIdx.x, pos = blockIdx.y, b = blockIdx.z;
    __shared__ float sp[16][256];
    __shared__ float sv[16][68];
    int tid = threadIdx.x, tx = tid & 15, ty = tid >> 4;
    float acc[16][4];
#pragma unroll
    for (int k = 0; k < 16; k++)
#pragma unroll
        for (int j = 0; j < 4; j++) acc[k][j] = 0.f;

    const float* pb = p + b * (NB * NB);
    for (int s0 = 0; s0 < 256; s0 += 16) {
        {   // sp[si][tb] = p[b][tb][s0+si] ; thread tid handles tb=tid
            const float4* src = (const float4*)(pb + (size_t)tid * 256 + s0);
#pragma unroll
            for (int q = 0; q < 4; q++) {
                float4 v = src[q];
                sp[q * 4 + 0][tid] = v.x; sp[q * 4 + 1][tid] = v.y;
                sp[q * 4 + 2][tid] = v.z; sp[q * 4 + 3][tid] = v.w;
            }
        }
        {   // sv[si][0..64) = value rows 16*(s0+si)+pos, cols et*64..
            int si = tid >> 4, j = tid & 15;
            float4 v = *(const float4*)(value +
                (size_t)((s0 + si) * BUCKET + pos) * (B_DIM * E_DIM) + b * E_DIM + et * 64 + j * 4);
            *(float4*)&sv[si][j * 4] = v;
        }
        __syncthreads();
#pragma unroll
        for (int si = 0; si < 16; si++) {
            float4 rv = *(float4*)&sv[si][tx * 4];
#pragma unroll
            for (int k = 0; k < 16; k++) {
                float a = sp[si][ty + (k << 4)];
                acc[k][0] = fmaf(a, rv.x, acc[k][0]);
                acc[k][1] = fmaf(a, rv.y, acc[k][1]);
                acc[k][2] = fmaf(a, rv.z, acc[k][2]);
                acc[k][3] = fmaf(a, rv.w, acc[k][3]);
            }
        }
        __syncthreads();
    }
#pragma unroll
    for (int k = 0; k < 16; k++) {
        int tb = k * 16 + ty;
        size_t off = (size_t)((tb * BUCKET + pos) * B_DIM + b) * E_DIM + et * 64 + tx * 4;
        *(float4*)(Z + off) = make_float4(acc[k][0], acc[k][1], acc[k][2], acc[k][3]);
    }
}

// ---------------- launch ----------------
extern "C" void kernel_launch(void* const* d_in, const int* in_sizes, int n_in,
                              void* d_out, int out_size) {
    const float* query = (const float*)d_in[0];
    const float* key_t = (const float*)d_in[1];
    const float* value = (const float*)d_in[2];
    const unsigned char* kpm = (const unsigned char*)d_in[3];
    const float* Wq = (const float*)d_in[4];
    const float* bq = (const float*)d_in[5];
    const float* Wk = (const float*)d_in[6];
    const float* bk = (const float*)d_in[7];
    const float* Wv = (const float*)d_in[8];
    const float* bv = (const float*)d_in[9];
    const float* Wo = (const float*)d_in[10];
    const float* bo = (const float*)d_in[11];
    float* out = (float*)d_out;

    float *qm, *km, *qb, *kb, *la, *p, *rowsum, *wvo, *bvo, *z;
    int* kpmb;
    cudaGetSymbolAddress((void**)&qm, g_qm);
    cudaGetSymbolAddress((void**)&km, g_km);
    cudaGetSymbolAddress((void**)&qb, g_qb);
    cudaGetSymbolAddress((void**)&kb, g_kb);
    cudaGetSymbolAddress((void**)&la, g_la);
    cudaGetSymbolAddress((void**)&p, g_p);
    cudaGetSymbolAddress((void**)&rowsum, g_rowsum);
    cudaGetSymbolAddress((void**)&kpmb, g_kpmb);
    cudaGetSymbolAddress((void**)&wvo, g_wvo);
    cudaGetSymbolAddress((void**)&bvo, g_bvo);
    cudaGetSymbolAddress((void**)&z, g_z);

    // 1) bucket means of raw query/key
    bucket_mean_kernel<<<(B_DIM * NB * E_DIM) / 256, 256>>>(query, qm);
    bucket_mean_kernel<<<(B_DIM * NB * E_DIM) / 256, 256>>>(key_t, km);

    // 2) project bucket means: qb = qm @ Wq^T + bq ; kb = km @ Wk^T + bk   (M=2048,N=1024,K=1024)
    gemm128_kernel<false, true, false><<<dim3(8, 16, 1), 256>>>(
        qb, qm, Wq, bq, nullptr, nullptr, 2048, 1024, 1024, 1.0f, 0, 0, 0);
    gemm128_kernel<false, true, false><<<dim3(8, 16, 1), 256>>>(
        kb, km, Wk, bk, nullptr, nullptr, 2048, 1024, 1024, 1.0f, 0, 0, 0);

    // 3) fold Wv into Wo:  wvo = Wo @ Wv  (reads Wv as (K,N)) ; bvo = Wo @ bv
    gemm128_kernel<true, false, false><<<dim3(8, 8, 1), 256>>>(
        wvo, Wo, Wv, nullptr, nullptr, nullptr, 1024, 1024, 1024, 1.0f, 0, 0, 0);
    bvo_kernel<<<128, 256>>>(Wo, bv, bvo);

    // 4) attn logits: la[b,i,j] = (qb . kb) * SCALE / TAU  (batched, M=N=256, K=1024)
    gemm128_kernel<false, false, false><<<dim3(2, 2, B_DIM), 256>>>(
        la, qb, kb, nullptr, nullptr, nullptr, 256, 256, 1024, ATTN_ALPHA,
        (long)NB * E_DIM, (long)NB * E_DIM, (long)NB * NB);

    // 5) mask
    kpmb_kernel<<<8, 256>>>(kpm, kpmb);
    mask_kernel<<<(B_DIM * NB * NB) / 256, 256>>>(la, kpmb);

    // 6) sinkhorn (8 iters) -> p, rowsum
    sinkhorn_kernel<<<B_DIM, 1024>>>(la, p, rowsum);

    // 7) bucket mix on raw value -> Z (T,B,E)
    zmix_kernel<<<dim3(16, 16, B_DIM), 256>>>(value, p, z);

    // 8) final: out = Z @ wvo^T + rowsum*bvo + bo  (M=32768,N=1024,K=1024)
    gemm128_kernel<false, true, true><<<dim3(8, 256, 1), 256>>>(
        out, z, wvo, bo, bvo, rowsum, 32768, 1024, 1024, 1.0f, 0, 0, 0);
}